// round 4
// baseline (speedup 1.0000x reference)
#include <cuda_runtime.h>

#define BATCH 64
#define TLEN 2048
#define JLEN 128
#define DDIM 512

#define BT 256   // t tile
#define BJ 64    // j tile
#define BK 16    // k tile
#define NKB (DDIM / BK)  // 32

#define AS_STRIDE (BJ + 4)    // 68 floats
#define BS_STRIDE (BT + 4)    // 260 floats

// Scratch: sim[b][j][t], fp32, 64 MB
__device__ float g_sim[(size_t)BATCH * JLEN * TLEN];
__device__ float g_max[BATCH * JLEN];
__device__ float g_invden[BATCH * JLEN];

// ---------------------------------------------------------------------------
// Kernel 1: per-batch GEMM  sim[j][t] = sum_d (question[j][d]*w[d]) * context[t][d]
// Tile 64(j) x 256(t), BK=16, 256 threads, 8x8 microtile, double-buffered smem.
// Warp w (0..7) owns j rows [w*8, w*8+8); lane owns t = lane*4..+3 and +128..+131.
// A-fragment LDS is warp-uniform (broadcast); B-fragment lane stride 16B: conflict-free.
// ---------------------------------------------------------------------------
__global__ __launch_bounds__(256, 2) void gemm_kernel(
    const float* __restrict__ question,
    const float* __restrict__ context,
    const int* __restrict__ qlen,
    const int* __restrict__ clen,
    const float* __restrict__ weight)
{
    const int b  = blockIdx.z;
    const int j0 = blockIdx.y * BJ;
    const int t0 = blockIdx.x * BT;
    const int cl = clen[b];
    const int ql = qlen[b];
    if (t0 >= cl || j0 >= ql) return;

    __shared__ float As[2][BK][AS_STRIDE];
    __shared__ float Bs[2][BK][BS_STRIDE];
    __shared__ float ws[DDIM];

    const int tid = threadIdx.x;

    for (int i = tid; i < DDIM; i += 256) ws[i] = weight[i];
    __syncthreads();

    // global->smem staging assignments
    const int arow = tid >> 2;          // 0..63  (j within tile)
    const int acol = (tid & 3) << 2;    // 0,4,8,12 (k within k-block)
    const int brow = tid;               // 0..255 (t within tile)

    const float* Aptr = question + ((size_t)(b * JLEN + j0 + arow) * DDIM) + acol;
    const float* Bptr = context  + ((size_t)(b * TLEN + t0 + brow) * DDIM);

    // preload k-block 0 into buffer 0
    {
        float4 av = *reinterpret_cast<const float4*>(Aptr);
        float4 v0 = *reinterpret_cast<const float4*>(Bptr);
        float4 v1 = *reinterpret_cast<const float4*>(Bptr + 4);
        float4 v2 = *reinterpret_cast<const float4*>(Bptr + 8);
        float4 v3 = *reinterpret_cast<const float4*>(Bptr + 12);
        As[0][acol + 0][arow] = av.x * ws[acol + 0];
        As[0][acol + 1][arow] = av.y * ws[acol + 1];
        As[0][acol + 2][arow] = av.z * ws[acol + 2];
        As[0][acol + 3][arow] = av.w * ws[acol + 3];
        Bs[0][ 0][brow] = v0.x;  Bs[0][ 1][brow] = v0.y;  Bs[0][ 2][brow] = v0.z;  Bs[0][ 3][brow] = v0.w;
        Bs[0][ 4][brow] = v1.x;  Bs[0][ 5][brow] = v1.y;  Bs[0][ 6][brow] = v1.z;  Bs[0][ 7][brow] = v1.w;
        Bs[0][ 8][brow] = v2.x;  Bs[0][ 9][brow] = v2.y;  Bs[0][10][brow] = v2.z;  Bs[0][11][brow] = v2.w;
        Bs[0][12][brow] = v3.x;  Bs[0][13][brow] = v3.y;  Bs[0][14][brow] = v3.z;  Bs[0][15][brow] = v3.w;
    }
    __syncthreads();

    // compute-side mapping
    const int lane = tid & 31;
    const int warp = tid >> 5;
    const int jy8  = warp << 3;   // j fragment base: 0,8,...,56
    const int tx4  = lane << 2;   // t fragment base: 0..124 (second half +128)

    float acc[8][8];
    #pragma unroll
    for (int i = 0; i < 8; ++i)
        #pragma unroll
        for (int c = 0; c < 8; ++c) acc[i][c] = 0.0f;

    for (int kb = 0; kb < NKB; ++kb) {
        const int s = kb & 1;
        float4 nav, nb0, nb1, nb2, nb3;
        const bool more = (kb + 1 < NKB);
        if (more) {
            const float* ap = Aptr + (kb + 1) * BK;
            const float* bp = Bptr + (kb + 1) * BK;
            nav = *reinterpret_cast<const float4*>(ap);
            nb0 = *reinterpret_cast<const float4*>(bp);
            nb1 = *reinterpret_cast<const float4*>(bp + 4);
            nb2 = *reinterpret_cast<const float4*>(bp + 8);
            nb3 = *reinterpret_cast<const float4*>(bp + 12);
        }

        #pragma unroll
        for (int kk = 0; kk < BK; ++kk) {
            const float4 a0 = *reinterpret_cast<const float4*>(&As[s][kk][jy8]);
            const float4 a1 = *reinterpret_cast<const float4*>(&As[s][kk][jy8 + 4]);
            const float4 p0 = *reinterpret_cast<const float4*>(&Bs[s][kk][tx4]);
            const float4 p1 = *reinterpret_cast<const float4*>(&Bs[s][kk][tx4 + 128]);
            const float av8[8] = {a0.x, a0.y, a0.z, a0.w, a1.x, a1.y, a1.z, a1.w};
            const float bv8[8] = {p0.x, p0.y, p0.z, p0.w, p1.x, p1.y, p1.z, p1.w};
            #pragma unroll
            for (int i = 0; i < 8; ++i)
                #pragma unroll
                for (int c = 0; c < 8; ++c)
                    acc[i][c] += av8[i] * bv8[c];
        }

        if (more) {
            const int d = s ^ 1;
            const int kb1 = (kb + 1) * BK;
            As[d][acol + 0][arow] = nav.x * ws[kb1 + acol + 0];
            As[d][acol + 1][arow] = nav.y * ws[kb1 + acol + 1];
            As[d][acol + 2][arow] = nav.z * ws[kb1 + acol + 2];
            As[d][acol + 3][arow] = nav.w * ws[kb1 + acol + 3];
            Bs[d][ 0][brow] = nb0.x;  Bs[d][ 1][brow] = nb0.y;  Bs[d][ 2][brow] = nb0.z;  Bs[d][ 3][brow] = nb0.w;
            Bs[d][ 4][brow] = nb1.x;  Bs[d][ 5][brow] = nb1.y;  Bs[d][ 6][brow] = nb1.z;  Bs[d][ 7][brow] = nb1.w;
            Bs[d][ 8][brow] = nb2.x;  Bs[d][ 9][brow] = nb2.y;  Bs[d][10][brow] = nb2.z;  Bs[d][11][brow] = nb2.w;
            Bs[d][12][brow] = nb3.x;  Bs[d][13][brow] = nb3.y;  Bs[d][14][brow] = nb3.z;  Bs[d][15][brow] = nb3.w;
            __syncthreads();
        }
    }

    // epilogue: sim[b][j0+jy8+i][t0 + tx4 + {0..3}] and [+128 + {0..3}]
    #pragma unroll
    for (int i = 0; i < 8; ++i) {
        float* row = g_sim + ((size_t)(b * JLEN + j0 + jy8 + i)) * TLEN + t0 + tx4;
        float4 lo = make_float4(acc[i][0], acc[i][1], acc[i][2], acc[i][3]);
        float4 hi = make_float4(acc[i][4], acc[i][5], acc[i][6], acc[i][7]);
        *reinterpret_cast<float4*>(row)       = lo;
        *reinterpret_cast<float4*>(row + 128) = hi;
    }
}

// ---------------------------------------------------------------------------
// Kernel 2: per (b, j<qlen): max over t<clen, then sum of exp, store max & 1/sum
// ---------------------------------------------------------------------------
__device__ __forceinline__ float warpMax(float v) {
    #pragma unroll
    for (int o = 16; o > 0; o >>= 1) v = fmaxf(v, __shfl_xor_sync(0xffffffffu, v, o));
    return v;
}
__device__ __forceinline__ float warpSum(float v) {
    #pragma unroll
    for (int o = 16; o > 0; o >>= 1) v += __shfl_xor_sync(0xffffffffu, v, o);
    return v;
}

__global__ __launch_bounds__(256) void stats_kernel(
    const int* __restrict__ qlen,
    const int* __restrict__ clen)
{
    const int b = blockIdx.y;
    const int j = blockIdx.x;
    if (j >= qlen[b]) return;
    const int cl = clen[b];

    const float* row = g_sim + ((size_t)(b * JLEN + j)) * TLEN;
    const int tid = threadIdx.x;

    __shared__ float red[8];
    __shared__ float smax;

    float m = -3.4028235e38f;
    for (int t = tid; t < cl; t += 256) m = fmaxf(m, row[t]);
    m = warpMax(m);
    if ((tid & 31) == 0) red[tid >> 5] = m;
    __syncthreads();
    if (tid == 0) {
        float mm = red[0];
        #pragma unroll
        for (int i = 1; i < 8; ++i) mm = fmaxf(mm, red[i]);
        smax = mm;
    }
    __syncthreads();
    m = smax;

    float s = 0.0f;
    for (int t = tid; t < cl; t += 256) s += __expf(row[t] - m);
    s = warpSum(s);
    if ((tid & 31) == 0) red[tid >> 5] = s;
    __syncthreads();
    if (tid == 0) {
        float ss = 0.0f;
        #pragma unroll
        for (int i = 0; i < 8; ++i) ss += red[i];
        g_max[b * JLEN + j]    = m;
        g_invden[b * JLEN + j] = 1.0f / ss;
    }
}

// ---------------------------------------------------------------------------
// Kernel 3: out[b,t] = sum_{j<qlen} exp(sim[b][j][t]-max)*invden  (t<clen), else 0
// ---------------------------------------------------------------------------
__global__ __launch_bounds__(256) void out_kernel(
    const int* __restrict__ qlen,
    const int* __restrict__ clen,
    float* __restrict__ out)
{
    const int b = blockIdx.y;
    const int t = blockIdx.x * 256 + threadIdx.x;
    const int ql = qlen[b];
    const int cl = clen[b];

    __shared__ float sm[JLEN];
    __shared__ float sd[JLEN];
    for (int jj = threadIdx.x; jj < ql; jj += 256) {
        sm[jj] = g_max[b * JLEN + jj];
        sd[jj] = g_invden[b * JLEN + jj];
    }
    __syncthreads();

    float r = 0.0f;
    if (t < cl) {
        const float* col = g_sim + (size_t)b * JLEN * TLEN + t;
        #pragma unroll 4
        for (int jj = 0; jj < ql; ++jj)
            r += __expf(col[(size_t)jj * TLEN] - sm[jj]) * sd[jj];
    }
    out[b * TLEN + t] = r;
}

// ---------------------------------------------------------------------------
extern "C" void kernel_launch(void* const* d_in, const int* in_sizes, int n_in,
                              void* d_out, int out_size)
{
    const float* question = (const float*)d_in[0];
    const float* context  = (const float*)d_in[1];
    const int*   qlen     = (const int*)d_in[2];
    const int*   clen     = (const int*)d_in[3];
    const float* weight   = (const float*)d_in[4];
    float* out = (float*)d_out;

    dim3 g1(TLEN / BT, JLEN / BJ, BATCH);   // 8 x 2 x 64
    gemm_kernel<<<g1, 256>>>(question, context, qlen, clen, weight);

    dim3 g2(JLEN, BATCH);                   // 128 x 64
    stats_kernel<<<g2, 256>>>(qlen, clen);

    dim3 g3(TLEN / 256, BATCH);             // 8 x 64
    out_kernel<<<g3, 256>>>(qlen, clen, out);
}

// round 5
// speedup vs baseline: 1.1868x; 1.1868x over previous
#include <cuda_runtime.h>

#define BATCH 64
#define TLEN 2048
#define JLEN 128
#define DDIM 512

#define BT 256   // t tile
#define BJ 64    // j tile
#define BK 16    // k tile
#define NKB (DDIM / BK)  // 32

#define AS_STRIDE (BJ + 4)    // 68 floats
#define BS_STRIDE (BT + 4)    // 260 floats

// Scratch: sim[b][j][t], fp32, 64 MB
__device__ float g_sim[(size_t)BATCH * JLEN * TLEN];
__device__ float g_max[BATCH * JLEN];
__device__ float g_invden[BATCH * JLEN];

__device__ __forceinline__ void fma2(unsigned long long& acc,
                                     unsigned long long a,
                                     unsigned long long b) {
    asm("fma.rn.f32x2 %0, %1, %2, %0;" : "+l"(acc) : "l"(a), "l"(b));
}
__device__ __forceinline__ unsigned long long dup2(float a) {
    unsigned long long r;
    asm("mov.b64 %0, {%1, %1};" : "=l"(r) : "f"(a));
    return r;
}

// ---------------------------------------------------------------------------
// Kernel 1: per-batch GEMM  sim[j][t] = sum_d (question[j][d]*w[d]) * context[t][d]
// Tile 64(j) x 256(t), BK=16, 256 threads, 8x8 microtile, packed f32x2 FMA.
// Warp w (0..7): j rows [w*8, w*8+8) (A-fragment LDS is warp-uniform broadcast).
// Lane: t = lane*4..+3 and +128..+131 (B-fragment lane stride 16B, conflict-free).
// Single-buffered smem, register prefetch (round-3 structure).
// ---------------------------------------------------------------------------
__global__ __launch_bounds__(256, 2) void gemm_kernel(
    const float* __restrict__ question,
    const float* __restrict__ context,
    const int* __restrict__ qlen,
    const int* __restrict__ clen,
    const float* __restrict__ weight)
{
    const int b  = blockIdx.z;
    const int j0 = blockIdx.y * BJ;
    const int t0 = blockIdx.x * BT;
    const int cl = clen[b];
    const int ql = qlen[b];
    if (t0 >= cl || j0 >= ql) return;

    __shared__ float As[BK][AS_STRIDE];
    __shared__ float Bs[BK][BS_STRIDE];
    __shared__ float ws[DDIM];

    const int tid = threadIdx.x;

    for (int i = tid; i < DDIM; i += 256) ws[i] = weight[i];
    __syncthreads();

    // global->smem staging assignments
    const int arow = tid >> 2;          // 0..63  (j within tile)
    const int acol = (tid & 3) << 2;    // 0,4,8,12 (k within k-block)
    const int brow = tid;               // 0..255 (t within tile)

    const float* Aptr = question + ((size_t)(b * JLEN + j0 + arow) * DDIM) + acol;
    const float* Bptr = context  + ((size_t)(b * TLEN + t0 + brow) * DDIM);

    // preload k-block 0
    {
        float4 av = *reinterpret_cast<const float4*>(Aptr);
        float4 v0 = *reinterpret_cast<const float4*>(Bptr);
        float4 v1 = *reinterpret_cast<const float4*>(Bptr + 4);
        float4 v2 = *reinterpret_cast<const float4*>(Bptr + 8);
        float4 v3 = *reinterpret_cast<const float4*>(Bptr + 12);
        As[acol + 0][arow] = av.x * ws[acol + 0];
        As[acol + 1][arow] = av.y * ws[acol + 1];
        As[acol + 2][arow] = av.z * ws[acol + 2];
        As[acol + 3][arow] = av.w * ws[acol + 3];
        Bs[ 0][brow] = v0.x;  Bs[ 1][brow] = v0.y;  Bs[ 2][brow] = v0.z;  Bs[ 3][brow] = v0.w;
        Bs[ 4][brow] = v1.x;  Bs[ 5][brow] = v1.y;  Bs[ 6][brow] = v1.z;  Bs[ 7][brow] = v1.w;
        Bs[ 8][brow] = v2.x;  Bs[ 9][brow] = v2.y;  Bs[10][brow] = v2.z;  Bs[11][brow] = v2.w;
        Bs[12][brow] = v3.x;  Bs[13][brow] = v3.y;  Bs[14][brow] = v3.z;  Bs[15][brow] = v3.w;
    }
    __syncthreads();

    // compute-side mapping
    const int lane = tid & 31;
    const int warp = tid >> 5;
    const int jy8  = warp << 3;   // j fragment base: 0,8,...,56 (warp-uniform)
    const int tx4  = lane << 2;   // t fragment base: 0..124 (second half +128)

    // 8 j x 8 t accumulators as 8 x 4 packed f32x2 (t pairs)
    unsigned long long acc2[8][4];
    #pragma unroll
    for (int i = 0; i < 8; ++i)
        #pragma unroll
        for (int c = 0; c < 4; ++c) acc2[i][c] = 0ull;

    for (int kb = 0; kb < NKB; ++kb) {
        float4 nav, nb0, nb1, nb2, nb3;
        const bool more = (kb + 1 < NKB);
        if (more) {
            const float* ap = Aptr + (kb + 1) * BK;
            const float* bp = Bptr + (kb + 1) * BK;
            nav = *reinterpret_cast<const float4*>(ap);
            nb0 = *reinterpret_cast<const float4*>(bp);
            nb1 = *reinterpret_cast<const float4*>(bp + 4);
            nb2 = *reinterpret_cast<const float4*>(bp + 8);
            nb3 = *reinterpret_cast<const float4*>(bp + 12);
        }

        #pragma unroll
        for (int kk = 0; kk < BK; ++kk) {
            const float4 a0 = *reinterpret_cast<const float4*>(&As[kk][jy8]);
            const float4 a1 = *reinterpret_cast<const float4*>(&As[kk][jy8 + 4]);
            const float4 p0 = *reinterpret_cast<const float4*>(&Bs[kk][tx4]);
            const float4 p1 = *reinterpret_cast<const float4*>(&Bs[kk][tx4 + 128]);

            unsigned long long bp2[4];
            bp2[0] = *reinterpret_cast<const unsigned long long*>(&p0.x);
            bp2[1] = *reinterpret_cast<const unsigned long long*>(&p0.z);
            bp2[2] = *reinterpret_cast<const unsigned long long*>(&p1.x);
            bp2[3] = *reinterpret_cast<const unsigned long long*>(&p1.z);

            const float av8[8] = {a0.x, a0.y, a0.z, a0.w, a1.x, a1.y, a1.z, a1.w};
            #pragma unroll
            for (int i = 0; i < 8; ++i) {
                const unsigned long long av2 = dup2(av8[i]);
                #pragma unroll
                for (int c = 0; c < 4; ++c)
                    fma2(acc2[i][c], av2, bp2[c]);
            }
        }

        if (more) {
            __syncthreads();
            const int kb1 = (kb + 1) * BK;
            As[acol + 0][arow] = nav.x * ws[kb1 + acol + 0];
            As[acol + 1][arow] = nav.y * ws[kb1 + acol + 1];
            As[acol + 2][arow] = nav.z * ws[kb1 + acol + 2];
            As[acol + 3][arow] = nav.w * ws[kb1 + acol + 3];
            Bs[ 0][brow] = nb0.x;  Bs[ 1][brow] = nb0.y;  Bs[ 2][brow] = nb0.z;  Bs[ 3][brow] = nb0.w;
            Bs[ 4][brow] = nb1.x;  Bs[ 5][brow] = nb1.y;  Bs[ 6][brow] = nb1.z;  Bs[ 7][brow] = nb1.w;
            Bs[ 8][brow] = nb2.x;  Bs[ 9][brow] = nb2.y;  Bs[10][brow] = nb2.z;  Bs[11][brow] = nb2.w;
            Bs[12][brow] = nb3.x;  Bs[13][brow] = nb3.y;  Bs[14][brow] = nb3.z;  Bs[15][brow] = nb3.w;
            __syncthreads();
        }
    }

    // epilogue: sim[b][j0+jy8+i][t0 + tx4 + {0..3}] and [+128 + {0..3}]
    #pragma unroll
    for (int i = 0; i < 8; ++i) {
        float* row = g_sim + ((size_t)(b * JLEN + j0 + jy8 + i)) * TLEN + t0 + tx4;
        const float2 x01 = *reinterpret_cast<const float2*>(&acc2[i][0]);
        const float2 x23 = *reinterpret_cast<const float2*>(&acc2[i][1]);
        const float2 x45 = *reinterpret_cast<const float2*>(&acc2[i][2]);
        const float2 x67 = *reinterpret_cast<const float2*>(&acc2[i][3]);
        *reinterpret_cast<float4*>(row)       = make_float4(x01.x, x01.y, x23.x, x23.y);
        *reinterpret_cast<float4*>(row + 128) = make_float4(x45.x, x45.y, x67.x, x67.y);
    }
}

// ---------------------------------------------------------------------------
// Kernel 2: per (b, j<qlen): max over t<clen, then sum of exp, store max & 1/sum
// ---------------------------------------------------------------------------
__device__ __forceinline__ float warpMax(float v) {
    #pragma unroll
    for (int o = 16; o > 0; o >>= 1) v = fmaxf(v, __shfl_xor_sync(0xffffffffu, v, o));
    return v;
}
__device__ __forceinline__ float warpSum(float v) {
    #pragma unroll
    for (int o = 16; o > 0; o >>= 1) v += __shfl_xor_sync(0xffffffffu, v, o);
    return v;
}

__global__ __launch_bounds__(256) void stats_kernel(
    const int* __restrict__ qlen,
    const int* __restrict__ clen)
{
    const int b = blockIdx.y;
    const int j = blockIdx.x;
    if (j >= qlen[b]) return;
    const int cl = clen[b];

    const float* row = g_sim + ((size_t)(b * JLEN + j)) * TLEN;
    const int tid = threadIdx.x;

    __shared__ float red[8];
    __shared__ float smax;

    float m = -3.4028235e38f;
    for (int t = tid; t < cl; t += 256) m = fmaxf(m, row[t]);
    m = warpMax(m);
    if ((tid & 31) == 0) red[tid >> 5] = m;
    __syncthreads();
    if (tid == 0) {
        float mm = red[0];
        #pragma unroll
        for (int i = 1; i < 8; ++i) mm = fmaxf(mm, red[i]);
        smax = mm;
    }
    __syncthreads();
    m = smax;

    float s = 0.0f;
    for (int t = tid; t < cl; t += 256) s += __expf(row[t] - m);
    s = warpSum(s);
    if ((tid & 31) == 0) red[tid >> 5] = s;
    __syncthreads();
    if (tid == 0) {
        float ss = 0.0f;
        #pragma unroll
        for (int i = 0; i < 8; ++i) ss += red[i];
        g_max[b * JLEN + j]    = m;
        g_invden[b * JLEN + j] = 1.0f / ss;
    }
}

// ---------------------------------------------------------------------------
// Kernel 3: out[b,t] = sum_{j<qlen} exp(sim[b][j][t]-max)*invden  (t<clen), else 0
// ---------------------------------------------------------------------------
__global__ __launch_bounds__(256) void out_kernel(
    const int* __restrict__ qlen,
    const int* __restrict__ clen,
    float* __restrict__ out)
{
    const int b = blockIdx.y;
    const int t = blockIdx.x * 256 + threadIdx.x;
    const int ql = qlen[b];
    const int cl = clen[b];

    __shared__ float sm[JLEN];
    __shared__ float sd[JLEN];
    for (int jj = threadIdx.x; jj < ql; jj += 256) {
        sm[jj] = g_max[b * JLEN + jj];
        sd[jj] = g_invden[b * JLEN + jj];
    }
    __syncthreads();

    float r = 0.0f;
    if (t < cl) {
        const float* col = g_sim + (size_t)b * JLEN * TLEN + t;
        #pragma unroll 4
        for (int jj = 0; jj < ql; ++jj)
            r += __expf(col[(size_t)jj * TLEN] - sm[jj]) * sd[jj];
    }
    out[b * TLEN + t] = r;
}

// ---------------------------------------------------------------------------
extern "C" void kernel_launch(void* const* d_in, const int* in_sizes, int n_in,
                              void* d_out, int out_size)
{
    const float* question = (const float*)d_in[0];
    const float* context  = (const float*)d_in[1];
    const int*   qlen     = (const int*)d_in[2];
    const int*   clen     = (const int*)d_in[3];
    const float* weight   = (const float*)d_in[4];
    float* out = (float*)d_out;

    dim3 g1(TLEN / BT, JLEN / BJ, BATCH);   // 8 x 2 x 64
    gemm_kernel<<<g1, 256>>>(question, context, qlen, clen, weight);

    dim3 g2(JLEN, BATCH);                   // 128 x 64
    stats_kernel<<<g2, 256>>>(qlen, clen);

    dim3 g3(TLEN / 256, BATCH);             // 8 x 64
    out_kernel<<<g3, 256>>>(qlen, clen, out);
}

// round 7
// speedup vs baseline: 1.6103x; 1.3569x over previous
#include <cuda_runtime.h>
#include <cuda_bf16.h>
#include <cstdint>

#define BATCH 64
#define TLEN 2048
#define JLEN 128
#define DDIM 512

#define TT   128              // t per CTA (N tile)
#define KC   64               // k per chunk (64 bf16 = 128B row, SW128 atom)
#define NCHUNK (DDIM / KC)    // 8

// smem offsets (bytes) within 64KB dynamic smem
#define A_HI 0
#define A_LO 16384
#define B_HI 32768
#define B_LO 49152
#define SM_TOTAL 65536

#define SWZ128(off) ((off) ^ (((off) >> 3) & 0x70))

// Scratch
__device__ float g_sim[(size_t)BATCH * JLEN * TLEN];
__device__ float g_max[BATCH * JLEN];
__device__ float g_invden[BATCH * JLEN];
__device__ __nv_bfloat16 g_qhi[(size_t)BATCH * JLEN * DDIM];  // (question*w) hi
__device__ __nv_bfloat16 g_qlo[(size_t)BATCH * JLEN * DDIM];  // (question*w) lo

// ---------------------------------------------------------------------------
// helpers
// ---------------------------------------------------------------------------
__device__ __forceinline__ uint32_t smem_u32(const void* p) {
    uint32_t a;
    asm("{ .reg .u64 t; cvta.to.shared.u64 t, %1; cvt.u32.u64 %0, t; }" : "=r"(a) : "l"(p));
    return a;
}

#define LDSM_X4(R, ADDR) \
    asm volatile("ldmatrix.sync.aligned.m8n8.x4.shared.b16 {%0,%1,%2,%3}, [%4];" \
        : "=r"((R)[0]), "=r"((R)[1]), "=r"((R)[2]), "=r"((R)[3]) : "r"(ADDR))

__device__ __forceinline__ void mma16816(float* d, const uint32_t* a, const uint32_t* b) {
    asm volatile(
        "mma.sync.aligned.m16n8k16.row.col.f32.bf16.bf16.f32 "
        "{%0,%1,%2,%3}, {%4,%5,%6,%7}, {%8,%9}, {%0,%1,%2,%3};"
        : "+f"(d[0]), "+f"(d[1]), "+f"(d[2]), "+f"(d[3])
        : "r"(a[0]), "r"(a[1]), "r"(a[2]), "r"(a[3]), "r"(b[0]), "r"(b[1]));
}

__device__ __forceinline__ uint32_t pack2bf(float a, float b) {
    __nv_bfloat16 ha = __float2bfloat16(a);
    __nv_bfloat16 hb = __float2bfloat16(b);
    return (uint32_t)__bfloat16_as_ushort(ha) | ((uint32_t)__bfloat16_as_ushort(hb) << 16);
}

// split float4 -> packed bf16 hi pair (h01,h23) and lo pair (l01,l23)
__device__ __forceinline__ void split4(const float4 v, uint32_t& h01, uint32_t& h23,
                                       uint32_t& l01, uint32_t& l23) {
    __nv_bfloat16 h0 = __float2bfloat16(v.x);
    __nv_bfloat16 h1 = __float2bfloat16(v.y);
    __nv_bfloat16 h2 = __float2bfloat16(v.z);
    __nv_bfloat16 h3 = __float2bfloat16(v.w);
    float r0 = v.x - __bfloat162float(h0);
    float r1 = v.y - __bfloat162float(h1);
    float r2 = v.z - __bfloat162float(h2);
    float r3 = v.w - __bfloat162float(h3);
    h01 = (uint32_t)__bfloat16_as_ushort(h0) | ((uint32_t)__bfloat16_as_ushort(h1) << 16);
    h23 = (uint32_t)__bfloat16_as_ushort(h2) | ((uint32_t)__bfloat16_as_ushort(h3) << 16);
    l01 = pack2bf(r0, r1);
    l23 = pack2bf(r2, r3);
}

// ---------------------------------------------------------------------------
// Kernel 0: split (question * w) into bf16 hi/lo global scratch
// grid = BATCH*JLEN blocks x 128 threads; thread handles 4 floats
// ---------------------------------------------------------------------------
__global__ __launch_bounds__(128) void prep_kernel(
    const float* __restrict__ question,
    const float* __restrict__ weight)
{
    const int row = blockIdx.x;            // b*128 + j
    const int k4  = threadIdx.x * 4;
    const float4 q = __ldg(reinterpret_cast<const float4*>(question + (size_t)row * DDIM + k4));
    const float4 w = __ldg(reinterpret_cast<const float4*>(weight + k4));
    float4 v = make_float4(q.x * w.x, q.y * w.y, q.z * w.z, q.w * w.w);
    uint32_t h01, h23, l01, l23;
    split4(v, h01, h23, l01, l23);
    *reinterpret_cast<uint2*>(g_qhi + (size_t)row * DDIM + k4) = make_uint2(h01, h23);
    *reinterpret_cast<uint2*>(g_qlo + (size_t)row * DDIM + k4) = make_uint2(l01, l23);
}

// ---------------------------------------------------------------------------
// Kernel 1: HMMA GEMM. CTA = (t-tile of 128, b). Output D[j=128][t=128].
// D = sum_k (q*w)[j][k] * ctx[t][k], 3-pass bf16 split, fp32 accum.
// 8 warps = 2(j) x 4(t); per warp 4 m16-tiles x 4 n8-tiles.
// ---------------------------------------------------------------------------
__global__ __launch_bounds__(256) void gemm_kernel(
    const float* __restrict__ context,
    const int* __restrict__ clen)
{
    extern __shared__ __align__(1024) char smem[];
    const int b  = blockIdx.y;
    const int t0 = blockIdx.x * TT;
    if (t0 >= clen[b]) return;

    const uint32_t sb = smem_u32(smem);
    const int tid  = threadIdx.x;
    const int lane = tid & 31;
    const int wid  = tid >> 5;

    const int jbase = (wid & 1) << 6;   // 0 or 64
    const int tbase = (wid >> 1) << 5;  // 0,32,64,96

    const int r    = lane & 7;
    const int quad = lane >> 3;

    float acc[4][4][4];
    #pragma unroll
    for (int mt = 0; mt < 4; ++mt)
        #pragma unroll
        for (int nt = 0; nt < 4; ++nt)
            #pragma unroll
            for (int i = 0; i < 4; ++i) acc[mt][nt][i] = 0.0f;

    for (int kb = 0; kb < DDIM; kb += KC) {
        // ---- stage A (question hi/lo, already bf16) : 128 rows x 64 k ----
        #pragma unroll
        for (int it = 0; it < 4; ++it) {
            const int idx = tid + it * 256;       // 0..1023
            const int row = idx >> 3;
            const int u   = idx & 7;              // 16B unit within row
            const size_t src = ((size_t)(b * JLEN + row)) * DDIM + kb + u * 8;
            const uint4 vh = *reinterpret_cast<const uint4*>(g_qhi + src);
            const uint4 vl = *reinterpret_cast<const uint4*>(g_qlo + src);
            const uint32_t off = SWZ128((uint32_t)(row * 128 + u * 16));
            *reinterpret_cast<uint4*>(smem + A_HI + off) = vh;
            *reinterpret_cast<uint4*>(smem + A_LO + off) = vl;
        }
        // ---- stage B (context, fp32 -> bf16 split) : 128 rows x 64 k ----
        #pragma unroll
        for (int it = 0; it < 8; ++it) {
            const int idx = tid + it * 256;       // 0..2047
            const int row = idx >> 4;
            const int u   = idx & 15;             // float4 unit within row
            const float4 c = __ldg(reinterpret_cast<const float4*>(
                context + ((size_t)(b * TLEN + t0 + row)) * DDIM + kb + u * 4));
            uint32_t h01, h23, l01, l23;
            split4(c, h01, h23, l01, l23);
            const uint32_t off = SWZ128((uint32_t)(row * 128 + u * 8));
            *reinterpret_cast<uint2*>(smem + B_HI + off) = make_uint2(h01, h23);
            *reinterpret_cast<uint2*>(smem + B_LO + off) = make_uint2(l01, l23);
        }
        __syncthreads();

        // ---- compute: 4 k16-steps ----
        #pragma unroll
        for (int ks = 0; ks < 4; ++ks) {
            // B fragments: 4 n8-tiles (hi & lo), 2 ldmatrix.x4 each
            uint32_t bh[8], bl[8];
            #pragma unroll
            for (int p = 0; p < 2; ++p) {
                const int tile  = p * 2 + (quad >> 1);
                const int khalf = quad & 1;
                const int rowt  = tbase + tile * 8 + r;
                const uint32_t off = SWZ128((uint32_t)(rowt * 128 + ks * 32 + khalf * 16));
                LDSM_X4(bh + p * 4, sb + B_HI + off);
                LDSM_X4(bl + p * 4, sb + B_LO + off);
            }
            // A fragments per m-tile, then 12 MMAs
            #pragma unroll
            for (int mt = 0; mt < 4; ++mt) {
                const int rowa = jbase + mt * 16 + ((quad & 1) << 3) + r;
                const uint32_t off = SWZ128((uint32_t)(rowa * 128 + ks * 32 + ((quad >> 1) << 4)));
                uint32_t ah[4], al[4];
                LDSM_X4(ah, sb + A_HI + off);
                LDSM_X4(al, sb + A_LO + off);
                #pragma unroll
                for (int nt = 0; nt < 4; ++nt) {
                    mma16816(acc[mt][nt], ah, bh + nt * 2);
                    mma16816(acc[mt][nt], al, bh + nt * 2);
                    mma16816(acc[mt][nt], ah, bl + nt * 2);
                }
            }
        }
        __syncthreads();
    }

    // ---- epilogue: D[j][t] -> g_sim[b][j][t0+t] ----
    const int g   = lane >> 2;
    const int tig = lane & 3;
    #pragma unroll
    for (int mt = 0; mt < 4; ++mt) {
        const int j = jbase + mt * 16 + g;
        #pragma unroll
        for (int nt = 0; nt < 4; ++nt) {
            const int t = t0 + tbase + nt * 8 + tig * 2;
            float* p0 = g_sim + ((size_t)(b * JLEN + j)) * TLEN + t;
            *reinterpret_cast<float2*>(p0) = make_float2(acc[mt][nt][0], acc[mt][nt][1]);
            *reinterpret_cast<float2*>(p0 + 8 * TLEN) = make_float2(acc[mt][nt][2], acc[mt][nt][3]);
        }
    }
}

// ---------------------------------------------------------------------------
// Kernel 2: per (b, j<qlen): max over t<clen, then sum of exp -> max, 1/sum
// ---------------------------------------------------------------------------
__device__ __forceinline__ float warpMax(float v) {
    #pragma unroll
    for (int o = 16; o > 0; o >>= 1) v = fmaxf(v, __shfl_xor_sync(0xffffffffu, v, o));
    return v;
}
__device__ __forceinline__ float warpSum(float v) {
    #pragma unroll
    for (int o = 16; o > 0; o >>= 1) v += __shfl_xor_sync(0xffffffffu, v, o);
    return v;
}

__global__ __launch_bounds__(256) void stats_kernel(
    const int* __restrict__ qlen,
    const int* __restrict__ clen)
{
    const int b = blockIdx.y;
    const int j = blockIdx.x;
    if (j >= qlen[b]) return;
    const int cl = clen[b];

    const float* row = g_sim + ((size_t)(b * JLEN + j)) * TLEN;
    const int tid = threadIdx.x;

    __shared__ float red[8];
    __shared__ float smax;

    float m = -3.4028235e38f;
    for (int t = tid; t < cl; t += 256) m = fmaxf(m, row[t]);
    m = warpMax(m);
    if ((tid & 31) == 0) red[tid >> 5] = m;
    __syncthreads();
    if (tid == 0) {
        float mm = red[0];
        #pragma unroll
        for (int i = 1; i < 8; ++i) mm = fmaxf(mm, red[i]);
        smax = mm;
    }
    __syncthreads();
    m = smax;

    float s = 0.0f;
    for (int t = tid; t < cl; t += 256) s += __expf(row[t] - m);
    s = warpSum(s);
    if ((tid & 31) == 0) red[tid >> 5] = s;
    __syncthreads();
    if (tid == 0) {
        float ss = 0.0f;
        #pragma unroll
        for (int i = 0; i < 8; ++i) ss += red[i];
        g_max[b * JLEN + j]    = m;
        g_invden[b * JLEN + j] = 1.0f / ss;
    }
}

// ---------------------------------------------------------------------------
// Kernel 3: out[b,t] = sum_{j<qlen} exp(sim[b][j][t]-max)*invden (t<clen), else 0
// ---------------------------------------------------------------------------
__global__ __launch_bounds__(256) void out_kernel(
    const int* __restrict__ qlen,
    const int* __restrict__ clen,
    float* __restrict__ out)
{
    const int b = blockIdx.y;
    const int t = blockIdx.x * 256 + threadIdx.x;
    const int ql = qlen[b];
    const int cl = clen[b];

    __shared__ float sm[JLEN];
    __shared__ float sd[JLEN];
    for (int jj = threadIdx.x; jj < ql; jj += 256) {
        sm[jj] = g_max[b * JLEN + jj];
        sd[jj] = g_invden[b * JLEN + jj];
    }
    __syncthreads();

    float r = 0.0f;
    if (t < cl) {
        const float* col = g_sim + (size_t)b * JLEN * TLEN + t;
        #pragma unroll 4
        for (int jj = 0; jj < ql; ++jj)
            r += __expf(col[(size_t)jj * TLEN] - sm[jj]) * sd[jj];
    }
    out[b * TLEN + t] = r;
}

// ---------------------------------------------------------------------------
extern "C" void kernel_launch(void* const* d_in, const int* in_sizes, int n_in,
                              void* d_out, int out_size)
{
    const float* question = (const float*)d_in[0];
    const float* context  = (const float*)d_in[1];
    const int*   qlen     = (const int*)d_in[2];
    const int*   clen     = (const int*)d_in[3];
    const float* weight   = (const float*)d_in[4];
    float* out = (float*)d_out;

    cudaFuncSetAttribute(gemm_kernel, cudaFuncAttributeMaxDynamicSharedMemorySize, SM_TOTAL);

    prep_kernel<<<BATCH * JLEN, 128>>>(question, weight);

    dim3 g1(TLEN / TT, BATCH);              // 16 x 64
    gemm_kernel<<<g1, 256, SM_TOTAL>>>(context, clen);

    dim3 g2(JLEN, BATCH);                   // 128 x 64
    stats_kernel<<<g2, 256>>>(qlen, clen);

    dim3 g3(TLEN / 256, BATCH);             // 8 x 64
    out_kernel<<<g3, 256>>>(qlen, clen, out);
}

// round 8
// speedup vs baseline: 2.1575x; 1.3398x over previous
#include <cuda_runtime.h>
#include <cuda_bf16.h>
#include <cstdint>

#define BATCH 64
#define TLEN 2048
#define JLEN 128
#define DDIM 512

#define TT   128              // t per CTA (N tile)
#define KC   64               // k per chunk (64 bf16 = 128B row, SW128 atom)

// smem offsets (bytes) within 64KB dynamic smem
#define A_HI 0
#define A_LO 16384
#define B_HI 32768
#define B_LO 49152
#define SM_TOTAL 65536

#define SWZ128(off) ((off) ^ (((off) >> 3) & 0x70))

// Scratch
__device__ float g_sim[(size_t)BATCH * JLEN * TLEN];
__device__ float g_max[BATCH * JLEN];
__device__ float g_invden[BATCH * JLEN];
__device__ __nv_bfloat16 g_qhi[(size_t)BATCH * JLEN * DDIM];  // (question*w) hi
__device__ __nv_bfloat16 g_qlo[(size_t)BATCH * JLEN * DDIM];  // (question*w) lo

// ---------------------------------------------------------------------------
// helpers
// ---------------------------------------------------------------------------
__device__ __forceinline__ uint32_t smem_u32(const void* p) {
    uint32_t a;
    asm("{ .reg .u64 t; cvta.to.shared.u64 t, %1; cvt.u32.u64 %0, t; }" : "=r"(a) : "l"(p));
    return a;
}

#define LDSM_X4(R, ADDR) \
    asm volatile("ldmatrix.sync.aligned.m8n8.x4.shared.b16 {%0,%1,%2,%3}, [%4];" \
        : "=r"((R)[0]), "=r"((R)[1]), "=r"((R)[2]), "=r"((R)[3]) : "r"(ADDR))

__device__ __forceinline__ void mma16816(float* d, const uint32_t* a, const uint32_t* b) {
    asm volatile(
        "mma.sync.aligned.m16n8k16.row.col.f32.bf16.bf16.f32 "
        "{%0,%1,%2,%3}, {%4,%5,%6,%7}, {%8,%9}, {%0,%1,%2,%3};"
        : "+f"(d[0]), "+f"(d[1]), "+f"(d[2]), "+f"(d[3])
        : "r"(a[0]), "r"(a[1]), "r"(a[2]), "r"(a[3]), "r"(b[0]), "r"(b[1]));
}

__device__ __forceinline__ uint32_t pack2bf(float a, float b) {
    __nv_bfloat16 ha = __float2bfloat16(a);
    __nv_bfloat16 hb = __float2bfloat16(b);
    return (uint32_t)__bfloat16_as_ushort(ha) | ((uint32_t)__bfloat16_as_ushort(hb) << 16);
}

// split float4 -> packed bf16 hi pair (h01,h23) and lo pair (l01,l23)
__device__ __forceinline__ void split4(const float4 v, uint32_t& h01, uint32_t& h23,
                                       uint32_t& l01, uint32_t& l23) {
    __nv_bfloat16 h0 = __float2bfloat16(v.x);
    __nv_bfloat16 h1 = __float2bfloat16(v.y);
    __nv_bfloat16 h2 = __float2bfloat16(v.z);
    __nv_bfloat16 h3 = __float2bfloat16(v.w);
    float r0 = v.x - __bfloat162float(h0);
    float r1 = v.y - __bfloat162float(h1);
    float r2 = v.z - __bfloat162float(h2);
    float r3 = v.w - __bfloat162float(h3);
    h01 = (uint32_t)__bfloat16_as_ushort(h0) | ((uint32_t)__bfloat16_as_ushort(h1) << 16);
    h23 = (uint32_t)__bfloat16_as_ushort(h2) | ((uint32_t)__bfloat16_as_ushort(h3) << 16);
    l01 = pack2bf(r0, r1);
    l23 = pack2bf(r2, r3);
}

// ---------------------------------------------------------------------------
// Kernel 0: split (question * w) into bf16 hi/lo global scratch
// ---------------------------------------------------------------------------
__global__ __launch_bounds__(128) void prep_kernel(
    const float* __restrict__ question,
    const float* __restrict__ weight)
{
    const int row = blockIdx.x;            // b*128 + j
    const int k4  = threadIdx.x * 4;
    const float4 q = __ldg(reinterpret_cast<const float4*>(question + (size_t)row * DDIM + k4));
    const float4 w = __ldg(reinterpret_cast<const float4*>(weight + k4));
    float4 v = make_float4(q.x * w.x, q.y * w.y, q.z * w.z, q.w * w.w);
    uint32_t h01, h23, l01, l23;
    split4(v, h01, h23, l01, l23);
    *reinterpret_cast<uint2*>(g_qhi + (size_t)row * DDIM + k4) = make_uint2(h01, h23);
    *reinterpret_cast<uint2*>(g_qlo + (size_t)row * DDIM + k4) = make_uint2(l01, l23);
}

// ---------------------------------------------------------------------------
// Kernel 1: HMMA GEMM. CTA = (t-tile of 128, b). Output D[j<ql(128)][t=128].
// 3-pass bf16 split, fp32 accum. 8 warps = 2(j) x 4(t); warp: 4 m16 x 4 n8.
// j-tiles with base >= qlen are skipped (A-ldsm, MMAs, epilogue stores).
// ---------------------------------------------------------------------------
__global__ __launch_bounds__(256) void gemm_kernel(
    const float* __restrict__ context,
    const int* __restrict__ qlen,
    const int* __restrict__ clen)
{
    extern __shared__ __align__(1024) char smem[];
    const int b  = blockIdx.y;
    const int t0 = blockIdx.x * TT;
    if (t0 >= clen[b]) return;
    const int ql = qlen[b];
    const int qlr = (ql + 15) & ~15;    // rounded to m16 tiles

    const uint32_t sb = smem_u32(smem);
    const int tid  = threadIdx.x;
    const int lane = tid & 31;
    const int wid  = tid >> 5;

    const int jbase = (wid & 1) << 6;   // 0 or 64
    const int tbase = (wid >> 1) << 5;  // 0,32,64,96

    const int r    = lane & 7;
    const int quad = lane >> 3;

    float acc[4][4][4];
    #pragma unroll
    for (int mt = 0; mt < 4; ++mt)
        #pragma unroll
        for (int nt = 0; nt < 4; ++nt)
            #pragma unroll
            for (int i = 0; i < 4; ++i) acc[mt][nt][i] = 0.0f;

    for (int kb = 0; kb < DDIM; kb += KC) {
        // ---- stage A (question hi/lo bf16) : rows < qlr only ----
        #pragma unroll
        for (int it = 0; it < 4; ++it) {
            const int idx = tid + it * 256;       // 0..1023
            const int row = idx >> 3;
            const int u   = idx & 7;              // 16B unit within row
            if (row < qlr) {
                const size_t src = ((size_t)(b * JLEN + row)) * DDIM + kb + u * 8;
                const uint4 vh = *reinterpret_cast<const uint4*>(g_qhi + src);
                const uint4 vl = *reinterpret_cast<const uint4*>(g_qlo + src);
                const uint32_t off = SWZ128((uint32_t)(row * 128 + u * 16));
                *reinterpret_cast<uint4*>(smem + A_HI + off) = vh;
                *reinterpret_cast<uint4*>(smem + A_LO + off) = vl;
            }
        }
        // ---- stage B (context fp32 -> bf16 split) : 128 rows x 64 k ----
        #pragma unroll
        for (int it = 0; it < 8; ++it) {
            const int idx = tid + it * 256;       // 0..2047
            const int row = idx >> 4;
            const int u   = idx & 15;             // float4 unit within row
            const float4 c = __ldg(reinterpret_cast<const float4*>(
                context + ((size_t)(b * TLEN + t0 + row)) * DDIM + kb + u * 4));
            uint32_t h01, h23, l01, l23;
            split4(c, h01, h23, l01, l23);
            const uint32_t off = SWZ128((uint32_t)(row * 128 + u * 8));
            *reinterpret_cast<uint2*>(smem + B_HI + off) = make_uint2(h01, h23);
            *reinterpret_cast<uint2*>(smem + B_LO + off) = make_uint2(l01, l23);
        }
        __syncthreads();

        // ---- compute: 4 k16-steps ----
        #pragma unroll
        for (int ks = 0; ks < 4; ++ks) {
            uint32_t bh[8], bl[8];
            #pragma unroll
            for (int p = 0; p < 2; ++p) {
                const int tile  = p * 2 + (quad >> 1);
                const int khalf = quad & 1;
                const int rowt  = tbase + tile * 8 + r;
                const uint32_t off = SWZ128((uint32_t)(rowt * 128 + ks * 32 + khalf * 16));
                LDSM_X4(bh + p * 4, sb + B_HI + off);
                LDSM_X4(bl + p * 4, sb + B_LO + off);
            }
            #pragma unroll
            for (int mt = 0; mt < 4; ++mt) {
                if (jbase + mt * 16 < ql) {
                    const int rowa = jbase + mt * 16 + ((quad & 1) << 3) + r;
                    const uint32_t off = SWZ128((uint32_t)(rowa * 128 + ks * 32 + ((quad >> 1) << 4)));
                    uint32_t ah[4], al[4];
                    LDSM_X4(ah, sb + A_HI + off);
                    LDSM_X4(al, sb + A_LO + off);
                    #pragma unroll
                    for (int nt = 0; nt < 4; ++nt) {
                        mma16816(acc[mt][nt], ah, bh + nt * 2);
                        mma16816(acc[mt][nt], al, bh + nt * 2);
                        mma16816(acc[mt][nt], ah, bl + nt * 2);
                    }
                }
            }
        }
        __syncthreads();
    }

    // ---- epilogue: D[j][t] -> g_sim[b][j][t0+t], only live j-tiles ----
    const int g   = lane >> 2;
    const int tig = lane & 3;
    #pragma unroll
    for (int mt = 0; mt < 4; ++mt) {
        if (jbase + mt * 16 < ql) {
            const int j = jbase + mt * 16 + g;
            #pragma unroll
            for (int nt = 0; nt < 4; ++nt) {
                const int t = t0 + tbase + nt * 8 + tig * 2;
                float* p0 = g_sim + ((size_t)(b * JLEN + j)) * TLEN + t;
                *reinterpret_cast<float2*>(p0) = make_float2(acc[mt][nt][0], acc[mt][nt][1]);
                *reinterpret_cast<float2*>(p0 + 8 * TLEN) = make_float2(acc[mt][nt][2], acc[mt][nt][3]);
            }
        }
    }
}

// ---------------------------------------------------------------------------
// Kernel 2: per (b, j<qlen): single-pass max + sum of exp (regs hold the row)
// ---------------------------------------------------------------------------
__device__ __forceinline__ float warpMax(float v) {
    #pragma unroll
    for (int o = 16; o > 0; o >>= 1) v = fmaxf(v, __shfl_xor_sync(0xffffffffu, v, o));
    return v;
}
__device__ __forceinline__ float warpSum(float v) {
    #pragma unroll
    for (int o = 16; o > 0; o >>= 1) v += __shfl_xor_sync(0xffffffffu, v, o);
    return v;
}

__global__ __launch_bounds__(256) void stats_kernel(
    const int* __restrict__ qlen,
    const int* __restrict__ clen)
{
    const int b = blockIdx.y;
    const int j = blockIdx.x;
    if (j >= qlen[b]) return;
    const int cl = clen[b];

    const float* row = g_sim + ((size_t)(b * JLEN + j)) * TLEN;
    const int tid = threadIdx.x;

    __shared__ float red[8];
    __shared__ float smax;

    // load all elements for this thread into registers (cl <= 2048, 256 thr -> <= 8)
    float v[8];
    #pragma unroll
    for (int i = 0; i < 8; ++i) {
        const int t = tid + i * 256;
        v[i] = (t < cl) ? row[t] : -3.4028235e38f;
    }

    float m = v[0];
    #pragma unroll
    for (int i = 1; i < 8; ++i) m = fmaxf(m, v[i]);
    m = warpMax(m);
    if ((tid & 31) == 0) red[tid >> 5] = m;
    __syncthreads();
    if (tid == 0) {
        float mm = red[0];
        #pragma unroll
        for (int i = 1; i < 8; ++i) mm = fmaxf(mm, red[i]);
        smax = mm;
    }
    __syncthreads();
    m = smax;

    float s = 0.0f;
    #pragma unroll
    for (int i = 0; i < 8; ++i) s += __expf(v[i] - m);   // dead lanes underflow to 0
    s = warpSum(s);
    if ((tid & 31) == 0) red[tid >> 5] = s;
    __syncthreads();
    if (tid == 0) {
        float ss = 0.0f;
        #pragma unroll
        for (int i = 0; i < 8; ++i) ss += red[i];
        g_max[b * JLEN + j]    = m;
        g_invden[b * JLEN + j] = 1.0f / ss;
    }
}

// ---------------------------------------------------------------------------
// Kernel 3: out[b,t] = sum_{j<qlen} exp(sim[b][j][t]-max)*invden (t<clen), else 0
// ---------------------------------------------------------------------------
__global__ __launch_bounds__(256) void out_kernel(
    const int* __restrict__ qlen,
    const int* __restrict__ clen,
    float* __restrict__ out)
{
    const int b = blockIdx.y;
    const int t = blockIdx.x * 256 + threadIdx.x;
    const int ql = qlen[b];
    const int cl = clen[b];

    __shared__ float sm[JLEN];
    __shared__ float sd[JLEN];
    for (int jj = threadIdx.x; jj < ql; jj += 256) {
        sm[jj] = g_max[b * JLEN + jj];
        sd[jj] = g_invden[b * JLEN + jj];
    }
    __syncthreads();

    float r0 = 0.0f, r1 = 0.0f;
    if (t < cl) {
        const float* col = g_sim + (size_t)b * JLEN * TLEN + t;
        int jj = 0;
        #pragma unroll 4
        for (; jj + 1 < ql; jj += 2) {
            r0 += __expf(col[(size_t)jj * TLEN] - sm[jj]) * sd[jj];
            r1 += __expf(col[(size_t)(jj + 1) * TLEN] - sm[jj + 1]) * sd[jj + 1];
        }
        if (jj < ql)
            r0 += __expf(col[(size_t)jj * TLEN] - sm[jj]) * sd[jj];
    }
    out[b * TLEN + t] = r0 + r1;
}

// ---------------------------------------------------------------------------
extern "C" void kernel_launch(void* const* d_in, const int* in_sizes, int n_in,
                              void* d_out, int out_size)
{
    const float* question = (const float*)d_in[0];
    const float* context  = (const float*)d_in[1];
    const int*   qlen     = (const int*)d_in[2];
    const int*   clen     = (const int*)d_in[3];
    const float* weight   = (const float*)d_in[4];
    float* out = (float*)d_out;

    cudaFuncSetAttribute(gemm_kernel, cudaFuncAttributeMaxDynamicSharedMemorySize, SM_TOTAL);

    prep_kernel<<<BATCH * JLEN, 128>>>(question, weight);

    dim3 g1(TLEN / TT, BATCH);              // 16 x 64
    gemm_kernel<<<g1, 256, SM_TOTAL>>>(context, qlen, clen);

    dim3 g2(JLEN, BATCH);                   // 128 x 64
    stats_kernel<<<g2, 256>>>(qlen, clen);

    dim3 g3(TLEN / 256, BATCH);             // 8 x 64
    out_kernel<<<g3, 256>>>(qlen, clen, out);
}